// round 1
// baseline (speedup 1.0000x reference)
#include <cuda_runtime.h>
#include <cstdint>

// Problem constants (fixed by dataset)
constexpr int NSRC0 = 200000;
constexpr int NDST0 = 50000;
constexpr int NDST1 = 10000;
constexpr int DIM   = 256;

// Static scratch (no allocation allowed)
__device__ float g_agg0[(size_t)NDST0 * DIM];
__device__ float g_h0  [(size_t)NDST0 * DIM];
__device__ float g_agg1[(size_t)NDST1 * DIM];
__device__ float g_h1  [(size_t)NDST1 * DIM];

// ---------------------------------------------------------------------------
// zero: float4 grid-stride-free fill
// ---------------------------------------------------------------------------
__global__ void zero_kernel(float* __restrict__ p, int n_floats) {
    int i = blockIdx.x * blockDim.x + threadIdx.x;
    if (i * 4 < n_floats) {
        ((float4*)p)[i] = make_float4(0.f, 0.f, 0.f, 0.f);
    }
}

// ---------------------------------------------------------------------------
// scatter: agg[dst[e]] += tab[src[e]]  (256 floats/edge), one warp per edge,
// vector reduction red.global.add.v4.f32 (sm_90+) to cut atomic count 4x.
// ---------------------------------------------------------------------------
__global__ void __launch_bounds__(256) scatter_kernel(
    const float* __restrict__ tab,
    const int*   __restrict__ src,
    const int*   __restrict__ dst,
    float*       __restrict__ agg,
    int E)
{
    int warp = (blockIdx.x * blockDim.x + threadIdx.x) >> 5;
    int lane = threadIdx.x & 31;
    if (warp >= E) return;
    int s = __ldg(src + warp);
    int d = __ldg(dst + warp);
    const float4* srow = (const float4*)(tab + (size_t)s * DIM);
    float4*       drow = (float4*)(agg + (size_t)d * DIM);
#pragma unroll
    for (int it = 0; it < 2; ++it) {
        float4 v = __ldg(srow + lane + it * 32);
        float* addr = (float*)(drow + lane + it * 32);
        asm volatile("red.global.add.v4.f32 [%0], {%1,%2,%3,%4};"
                     :: "l"(addr), "f"(v.x), "f"(v.y), "f"(v.z), "f"(v.w)
                     : "memory");
    }
}

// ---------------------------------------------------------------------------
// Generic tiled fp32 GEMM:
//   Cout[row, colOff+col] = act( A_z[row,:K] @ B_z + bias? + Cin? )
// blockIdx.z selects block-diagonal slice via element offsets zA (A col), zB
// (B matrix), zC (output col). Vectorized float4 smem loads, TMxTN microtile.
// ---------------------------------------------------------------------------
template<int BM, int BN, int BK, int TM, int TN, bool ACC, bool RELU, bool HASBIAS>
__global__ void __launch_bounds__((BM / TM) * (BN / TN)) sgemm_kernel(
    int M, int N, int K,
    const float* __restrict__ A, int lda, int zA,
    const float* __restrict__ B, int ldb, int zB,
    const float* __restrict__ bias,
    const float* __restrict__ Cin,
    float*       __restrict__ Cout, int ldc, int zC)
{
    constexpr int TX = BN / TN;
    constexpr int TY = BM / TM;
    constexpr int NT = TX * TY;

    __shared__ float As[BK][BM + 4];
    __shared__ float Bs[BK][BN];

    const int tid = threadIdx.x;
    const int tx = tid % TX;
    const int ty = tid / TX;
    const int rowBase = blockIdx.y * BM;
    const int colBase = blockIdx.x * BN;
    const int colOff  = blockIdx.z * zC;

    A += (size_t)blockIdx.z * zA;
    B += (size_t)blockIdx.z * zB;

    float acc[TM][TN];
#pragma unroll
    for (int i = 0; i < TM; i++)
#pragma unroll
        for (int j = 0; j < TN; j++) acc[i][j] = 0.f;

    for (int k0 = 0; k0 < K; k0 += BK) {
        constexpr int APER = (BM * BK / 4) / NT;
#pragma unroll
        for (int l = 0; l < APER; l++) {
            int idx = tid + l * NT;
            int r = idx / (BK / 4);
            int c = idx % (BK / 4);
            int grow = rowBase + r;
            float4 v = make_float4(0.f, 0.f, 0.f, 0.f);
            if (grow < M)
                v = *(const float4*)(A + (size_t)grow * lda + k0 + c * 4);
            As[c * 4 + 0][r] = v.x;
            As[c * 4 + 1][r] = v.y;
            As[c * 4 + 2][r] = v.z;
            As[c * 4 + 3][r] = v.w;
        }
        constexpr int BPER = (BK * BN / 4) / NT;
#pragma unroll
        for (int l = 0; l < BPER; l++) {
            int idx = tid + l * NT;
            int kr = idx / (BN / 4);
            int c  = idx % (BN / 4);
            *(float4*)&Bs[kr][c * 4] =
                *(const float4*)(B + (size_t)(k0 + kr) * ldb + colBase + c * 4);
        }
        __syncthreads();

#pragma unroll
        for (int k = 0; k < BK; k++) {
            float af[TM], bf[TN];
#pragma unroll
            for (int i = 0; i < TM; i += 4) {
                float4 t = *(const float4*)&As[k][ty * TM + i];
                af[i] = t.x; af[i + 1] = t.y; af[i + 2] = t.z; af[i + 3] = t.w;
            }
#pragma unroll
            for (int j = 0; j < TN; j += 4) {
                float4 t = *(const float4*)&Bs[k][tx * TN + j];
                bf[j] = t.x; bf[j + 1] = t.y; bf[j + 2] = t.z; bf[j + 3] = t.w;
            }
#pragma unroll
            for (int i = 0; i < TM; i++)
#pragma unroll
                for (int j = 0; j < TN; j++)
                    acc[i][j] = fmaf(af[i], bf[j], acc[i][j]);
        }
        __syncthreads();
    }

#pragma unroll
    for (int i = 0; i < TM; i++) {
        int row = rowBase + ty * TM + i;
        if (row < M) {
#pragma unroll
            for (int j = 0; j < TN; j += 4) {
                int col = colOff + colBase + tx * TN + j;
                float4 v = make_float4(acc[i][j], acc[i][j + 1], acc[i][j + 2], acc[i][j + 3]);
                if constexpr (HASBIAS) {
                    float4 bv = *(const float4*)(bias + col);
                    v.x += bv.x; v.y += bv.y; v.z += bv.z; v.w += bv.w;
                }
                if constexpr (ACC) {
                    float4 cv = *(const float4*)(Cin + (size_t)row * ldc + col);
                    v.x += cv.x; v.y += cv.y; v.z += cv.z; v.w += cv.w;
                }
                if constexpr (RELU) {
                    v.x = fmaxf(v.x, 0.f); v.y = fmaxf(v.y, 0.f);
                    v.z = fmaxf(v.z, 0.f); v.w = fmaxf(v.w, 0.f);
                }
                *(float4*)(Cout + (size_t)row * ldc + col) = v;
            }
        }
    }
}

// ---------------------------------------------------------------------------
// Link prediction head: out[g] = relu((h[s]*h[d]) @ pw1 + pb1) @ pw2 + pb2
// 16 pairs per block of 128 threads; pw1 read coalesced once per block.
// ---------------------------------------------------------------------------
__global__ void __launch_bounds__(128) pred_kernel(
    const float* __restrict__ h,
    const int*   __restrict__ ps, const int* __restrict__ pd,
    const int*   __restrict__ ns, const int* __restrict__ nd,
    const float* __restrict__ pw1, const float* __restrict__ pb1,
    const float* __restrict__ pw2, const float* __restrict__ pb2,
    float*       __restrict__ out, int npair)
{
    constexpr int P = 16;
    __shared__ float e[P][DIM];
    __shared__ float sred[P][4];

    int tid = threadIdx.x;
    int base = blockIdx.x * P;

#pragma unroll
    for (int p = 0; p < P; p++) {
        if (tid < 64) {
            int g = base + p;
            int s, d;
            if (g < npair) { s = __ldg(ps + g);       d = __ldg(pd + g); }
            else           { s = __ldg(ns + g - npair); d = __ldg(nd + g - npair); }
            const float4* hs = (const float4*)(h + (size_t)s * DIM);
            const float4* hd = (const float4*)(h + (size_t)d * DIM);
            float4 a = __ldg(hs + tid);
            float4 b = __ldg(hd + tid);
            *(float4*)&e[p][tid * 4] = make_float4(a.x * b.x, a.y * b.y, a.z * b.z, a.w * b.w);
        }
    }
    __syncthreads();

    float accp[P];
#pragma unroll
    for (int p = 0; p < P; p++) accp[p] = 0.f;

    for (int i = 0; i < DIM; i++) {
        float w = __ldg(pw1 + i * 128 + tid);
#pragma unroll
        for (int p = 0; p < P; p++) accp[p] = fmaf(e[p][i], w, accp[p]);
    }

    float w2  = __ldg(pw2 + tid);
    float b1v = __ldg(pb1 + tid);
    int lane = tid & 31;
    int wid  = tid >> 5;
#pragma unroll
    for (int p = 0; p < P; p++) {
        float z = fmaxf(accp[p] + b1v, 0.f) * w2;
#pragma unroll
        for (int o = 16; o > 0; o >>= 1) z += __shfl_down_sync(0xffffffffu, z, o);
        if (lane == 0) sred[p][wid] = z;
    }
    __syncthreads();
    if (tid < P) {
        out[base + tid] = sred[tid][0] + sred[tid][1] + sred[tid][2] + sred[tid][3] + pb2[0];
    }
}

// ---------------------------------------------------------------------------
// launch
// ---------------------------------------------------------------------------
extern "C" void kernel_launch(void* const* d_in, const int* in_sizes, int n_in,
                              void* d_out, int out_size)
{
    const float* x     = (const float*)d_in[0];
    const int* src0    = (const int*)d_in[1];
    const int* dst0    = (const int*)d_in[2];
    const int* src1    = (const int*)d_in[3];
    const int* dst1    = (const int*)d_in[4];
    const int* pos_src = (const int*)d_in[5];
    const int* pos_dst = (const int*)d_in[6];
    const int* neg_src = (const int*)d_in[7];
    const int* neg_dst = (const int*)d_in[8];
    const float* W0    = (const float*)d_in[9];
    const float* loop0 = (const float*)d_in[10];
    const float* b0    = (const float*)d_in[11];
    const float* W1    = (const float*)d_in[12];
    const float* loop1 = (const float*)d_in[13];
    const float* b1    = (const float*)d_in[14];
    const float* pw1   = (const float*)d_in[15];
    const float* pb1   = (const float*)d_in[16];
    const float* pw2   = (const float*)d_in[17];
    const float* pb2   = (const float*)d_in[18];

    const int E0 = in_sizes[1];
    const int E1 = in_sizes[3];
    const int NP = in_sizes[5];

    float *agg0, *h0, *agg1, *h1;
    cudaGetSymbolAddress((void**)&agg0, g_agg0);
    cudaGetSymbolAddress((void**)&h0,   g_h0);
    cudaGetSymbolAddress((void**)&agg1, g_agg1);
    cudaGetSymbolAddress((void**)&h1,   g_h1);

    float* out   = (float*)d_out;
    float* out_h = out + 2 * NP;   // [10000, 256] final embeddings

    // zero accumulators
    zero_kernel<<<(NDST0 * DIM / 4 + 255) / 256, 256>>>(agg0, NDST0 * DIM);
    zero_kernel<<<(NDST1 * DIM / 4 + 255) / 256, 256>>>(agg1, NDST1 * DIM);

    // layer 0: scatter raw x (linearity: transform after aggregation)
    scatter_kernel<<<(E0 + 7) / 8, 256>>>(x, src0, dst0, agg0, E0);

    // h0_pre = x[:50000] @ loop0 + b0
    {
        dim3 grid(DIM / 64, (NDST0 + 127) / 128, 1);
        sgemm_kernel<128, 64, 16, 8, 4, false, false, true><<<grid, 256>>>(
            NDST0, DIM, DIM, x, DIM, 0, loop0, DIM, 0, b0, nullptr, h0, DIM, 0);
    }
    // h0 = relu( bdd(agg0, W0) + h0_pre )
    {
        dim3 grid(1, (NDST0 + 63) / 64, 4);
        sgemm_kernel<64, 64, 16, 4, 4, true, true, false><<<grid, 256>>>(
            NDST0, 64, 64, agg0, DIM, 64, W0, 64, 64 * 64, nullptr, h0, h0, DIM, 64);
    }

    // layer 1
    scatter_kernel<<<(E1 + 7) / 8, 256>>>(h0, src1, dst1, agg1, E1);
    {
        dim3 grid(DIM / 64, (NDST1 + 127) / 128, 1);
        sgemm_kernel<128, 64, 16, 8, 4, false, false, true><<<grid, 256>>>(
            NDST1, DIM, DIM, h0, DIM, 0, loop1, DIM, 0, b1, nullptr, h1, DIM, 0);
    }
    {
        dim3 grid(1, (NDST1 + 63) / 64, 4);
        sgemm_kernel<64, 64, 16, 4, 4, true, true, false><<<grid, 256>>>(
            NDST1, 64, 64, agg1, DIM, 64, W1, 64, 64 * 64, nullptr, h1, out_h, DIM, 64);
    }

    // prediction head: 10000 pairs -> out[0:10000]
    pred_kernel<<<(2 * NP) / 16, 128>>>(out_h, pos_src, pos_dst, neg_src, neg_dst,
                                        pw1, pb1, pw2, pb2, out, NP);
}